// round 4
// baseline (speedup 1.0000x reference)
#include <cuda_runtime.h>
#include <cuda_bf16.h>
#include <cstddef>

// Problem shape (fixed for RNN_5188320494079): N=64, T=1024, D=256, H=256.
// Inputs (metadata order): x[N,T,D] f32, h0[N,H] f32, Wx[D,H] f32, Wh[H,H] f32, b[H] f32.
// Output: [N,T,H] f32.
//
// Plan:
//   Kernel 1: Out[n,t,:] = x[n,t,:] @ Wx + b   (big parallel GEMM, written in-place into d_out)
//   Kernel 2: per-batch sequential scan, 64 CTAs (one per n), updating d_out in place:
//             h_t = tanh(Out[n,t,:] + h_{t-1} @ Wh);  Out[n,t,:] = h_t

#define RNN_N 64
#define RNN_T 1024
#define RNN_D 256
#define RNN_H 256

// ---------------------------------------------------------------------------
// Kernel 1: classic smem-tiled SGEMM, BM=128 BN=128 BK=16, 256 thr, 8x8 micro.
// M = N*T = 65536 rows, K = 256, Ncols = 256. Grid (512, 2).
// ---------------------------------------------------------------------------
__global__ __launch_bounds__(256, 2)
void gemm_xw_kernel(const float* __restrict__ X, const float* __restrict__ Wx,
                    const float* __restrict__ bias, float* __restrict__ Out) {
    __shared__ float As[16][132];   // A stored transposed: As[k][m], pad keeps 16B align (132*4=528=33*16)
    __shared__ float Bs[16][128];

    const int tid = threadIdx.x;
    const int tx = tid & 15;        // output col group
    const int ty = tid >> 4;        // output row group
    const int m0 = blockIdx.x * 128;
    const int n0 = blockIdx.y * 128;

    const int a_row = tid >> 2;          // 0..63
    const int a_col = (tid & 3) << 2;    // 0,4,8,12
    const int b_row = tid >> 5;          // 0..7
    const int b_col = (tid & 31) << 2;   // 0..124

    float acc[8][8];
#pragma unroll
    for (int i = 0; i < 8; i++)
#pragma unroll
        for (int j = 0; j < 8; j++) acc[i][j] = 0.f;

    for (int k0 = 0; k0 < RNN_D; k0 += 16) {
        // issue gmem loads for this tile (overlaps previous tile's FMAs)
        float4 av0 = *reinterpret_cast<const float4*>(&X[(size_t)(m0 + a_row) * RNN_D + k0 + a_col]);
        float4 av1 = *reinterpret_cast<const float4*>(&X[(size_t)(m0 + a_row + 64) * RNN_D + k0 + a_col]);
        float4 bv0 = *reinterpret_cast<const float4*>(&Wx[(size_t)(k0 + b_row) * RNN_H + n0 + b_col]);
        float4 bv1 = *reinterpret_cast<const float4*>(&Wx[(size_t)(k0 + b_row + 8) * RNN_H + n0 + b_col]);
        __syncthreads();   // previous tile fully consumed before overwrite
        As[a_col + 0][a_row] = av0.x;
        As[a_col + 1][a_row] = av0.y;
        As[a_col + 2][a_row] = av0.z;
        As[a_col + 3][a_row] = av0.w;
        As[a_col + 0][a_row + 64] = av1.x;
        As[a_col + 1][a_row + 64] = av1.y;
        As[a_col + 2][a_row + 64] = av1.z;
        As[a_col + 3][a_row + 64] = av1.w;
        *reinterpret_cast<float4*>(&Bs[b_row][b_col]) = bv0;
        *reinterpret_cast<float4*>(&Bs[b_row + 8][b_col]) = bv1;
        __syncthreads();
#pragma unroll
        for (int k = 0; k < 16; k++) {
            float4 af0 = *reinterpret_cast<const float4*>(&As[k][ty * 8]);
            float4 af1 = *reinterpret_cast<const float4*>(&As[k][ty * 8 + 4]);
            float4 bf0 = *reinterpret_cast<const float4*>(&Bs[k][tx * 8]);
            float4 bf1 = *reinterpret_cast<const float4*>(&Bs[k][tx * 8 + 4]);
            float a_[8] = {af0.x, af0.y, af0.z, af0.w, af1.x, af1.y, af1.z, af1.w};
            float b_[8] = {bf0.x, bf0.y, bf0.z, bf0.w, bf1.x, bf1.y, bf1.z, bf1.w};
#pragma unroll
            for (int i = 0; i < 8; i++)
#pragma unroll
                for (int j = 0; j < 8; j++)
                    acc[i][j] += a_[i] * b_[j];
        }
    }

    float4 bb0 = *reinterpret_cast<const float4*>(&bias[n0 + tx * 8]);
    float4 bb1 = *reinterpret_cast<const float4*>(&bias[n0 + tx * 8 + 4]);
    float bb[8] = {bb0.x, bb0.y, bb0.z, bb0.w, bb1.x, bb1.y, bb1.z, bb1.w};
#pragma unroll
    for (int i = 0; i < 8; i++) {
        size_t r = (size_t)(m0 + ty * 8 + i) * RNN_H + n0 + tx * 8;
        float4 o0 = make_float4(acc[i][0] + bb[0], acc[i][1] + bb[1],
                                acc[i][2] + bb[2], acc[i][3] + bb[3]);
        float4 o1 = make_float4(acc[i][4] + bb[4], acc[i][5] + bb[5],
                                acc[i][6] + bb[6], acc[i][7] + bb[7]);
        *reinterpret_cast<float4*>(&Out[r]) = o0;
        *reinterpret_cast<float4*>(&Out[r + 4]) = o1;
    }
}

// ---------------------------------------------------------------------------
// Kernel 2: recurrence scan. 64 CTAs (one batch element each), 512 threads.
// Thread (q = tid>>6, jg = tid&63) computes partial[j] = sum_{i in q-octant}
// h[i]*Wh[i][j] for j = 4*jg..4*jg+3.
//   - 24 of its 32 i-values: Wh tile held in 96 registers (loaded once)
//   - remaining 8 i-values: __ldg float4 each step (64KB/CTA slice, L1-resident)
//   - h broadcast from smem (double-buffered), 8 partials reduced via smem
//   - xw_{t+1} prefetched with __ldcg (L2 path, no L1 pollution), h stored __stcs
// ---------------------------------------------------------------------------
__global__ __launch_bounds__(512, 1)
void rnn_scan_kernel(const float* __restrict__ h0,
                     const float* __restrict__ Wh,
                     float* Out) {
    __shared__ float hbuf[2][RNN_H];
    __shared__ float Psm[8][RNN_H];

    const int tid = threadIdx.x;
    const int n = blockIdx.x;
    const int jg = tid & 63;       // j group of 4 (warp-contiguous -> coalesced Wh loads)
    const int q = tid >> 6;        // i octant (warp-uniform -> h loads are broadcasts)
    const int j4 = jg * 4;
    const int ibase = q * 32;

    // Register-resident Wh tile: i = ibase..ibase+23, j = j4..j4+3 (96 regs)
    float wr[24][4];
#pragma unroll
    for (int k = 0; k < 24; k++) {
        float4 w = *reinterpret_cast<const float4*>(&Wh[(size_t)(ibase + k) * RNN_H + j4]);
        wr[k][0] = w.x; wr[k][1] = w.y; wr[k][2] = w.z; wr[k][3] = w.w;
    }
    // L1-serviced remainder rows i = ibase+24..ibase+31 (read every step)
    const float4* WhT = reinterpret_cast<const float4*>(Wh + (size_t)(ibase + 24) * RNN_H + j4);

    float* outn = Out + (size_t)n * RNN_T * RNN_H;
    float xw_cur = 0.f, xw_nxt = 0.f;
    if (tid < RNN_H) {
        hbuf[0][tid] = h0[(size_t)n * RNN_H + tid];
        xw_cur = __ldcg(&outn[tid]);            // xW at t=0 (written by kernel 1)
    }
    __syncthreads();

    int cur = 0;
    for (int t = 0; t < RNN_T; t++) {
        // prefetch next timestep's xW (lands well within this step's ~1300 cyc)
        if (tid < RNN_H && t + 1 < RNN_T)
            xw_nxt = __ldcg(&outn[(t + 1) * RNN_H + tid]);

        const float* hc = hbuf[cur];
        float a0 = 0.f, a1 = 0.f, a2 = 0.f, a3 = 0.f;

        // register-Wh part: 24 i-values (6 broadcast lds.128 for h)
#pragma unroll
        for (int kk = 0; kk < 6; kk++) {
            float4 hv = *reinterpret_cast<const float4*>(&hc[ibase + kk * 4]);
            a0 += hv.x * wr[kk * 4 + 0][0]; a1 += hv.x * wr[kk * 4 + 0][1];
            a2 += hv.x * wr[kk * 4 + 0][2]; a3 += hv.x * wr[kk * 4 + 0][3];
            a0 += hv.y * wr[kk * 4 + 1][0]; a1 += hv.y * wr[kk * 4 + 1][1];
            a2 += hv.y * wr[kk * 4 + 1][2]; a3 += hv.y * wr[kk * 4 + 1][3];
            a0 += hv.z * wr[kk * 4 + 2][0]; a1 += hv.z * wr[kk * 4 + 2][1];
            a2 += hv.z * wr[kk * 4 + 2][2]; a3 += hv.z * wr[kk * 4 + 2][3];
            a0 += hv.w * wr[kk * 4 + 3][0]; a1 += hv.w * wr[kk * 4 + 3][1];
            a2 += hv.w * wr[kk * 4 + 3][2]; a3 += hv.w * wr[kk * 4 + 3][3];
        }
        // L1-Wh part: 8 i-values
        {
            float4 h6 = *reinterpret_cast<const float4*>(&hc[ibase + 24]);
            float4 h7 = *reinterpret_cast<const float4*>(&hc[ibase + 28]);
            float hk[8] = {h6.x, h6.y, h6.z, h6.w, h7.x, h7.y, h7.z, h7.w};
#pragma unroll
            for (int k2 = 0; k2 < 8; k2++) {
                float4 w = __ldg(WhT + (size_t)k2 * (RNN_H / 4));
                a0 += hk[k2] * w.x; a1 += hk[k2] * w.y;
                a2 += hk[k2] * w.z; a3 += hk[k2] * w.w;
            }
        }

        *reinterpret_cast<float4*>(&Psm[q][j4]) = make_float4(a0, a1, a2, a3);
        __syncthreads();

        if (tid < RNN_H) {
            float z = xw_cur;
#pragma unroll
            for (int qq = 0; qq < 8; qq++) z += Psm[qq][tid];
            float hn = tanhf(z);
            hbuf[cur ^ 1][tid] = hn;
            __stcs(&outn[t * RNN_H + tid], hn);   // overwrite xW slot with h_t
            xw_cur = xw_nxt;
        }
        __syncthreads();   // h_{t+1} buffer visible; Psm free for reuse
        cur ^= 1;
    }
}

// ---------------------------------------------------------------------------
extern "C" void kernel_launch(void* const* d_in, const int* in_sizes, int n_in,
                              void* d_out, int out_size) {
    const float* x  = (const float*)d_in[0];   // [N,T,D]
    const float* h0 = (const float*)d_in[1];   // [N,H]
    const float* Wx = (const float*)d_in[2];   // [D,H]
    const float* Wh = (const float*)d_in[3];   // [H,H]
    const float* b  = (const float*)d_in[4];   // [H]
    float* out = (float*)d_out;                // [N,T,H]

    (void)in_sizes; (void)n_in; (void)out_size;

    // 1) xW + b  -> d_out  (M = N*T = 65536 rows; grid 512 x 2)
    dim3 g1(( RNN_N * RNN_T) / 128, RNN_H / 128);
    gemm_xw_kernel<<<g1, 256>>>(x, Wx, b, out);

    // 2) in-place sequential scan, one CTA per batch element
    rnn_scan_kernel<<<RNN_N, 512>>>(h0, Wh, out);
}